// round 1
// baseline (speedup 1.0000x reference)
#include <cuda_runtime.h>
#include <math.h>
#include <stdint.h>

// ============================================================================
// TemporalSamplingUpSampler
//
// out[c, tt] = A[c, k] * m(k, j)   where slot = floor(tt * total / T) (double),
// k = segment of slot, j = local offset, m = bilinear edge weight of a
// grid_sample on a width-constant input (interior == 1.0).
//
// Kernel 1 (1 block): softmax(L) -> Lp = T*softmax, r = rint(Lp) clamped >=0,
//                     exclusive prefix sum cum[], total, l_max.
// Kernel 2 (grid):    per output column compute (k, w) then broadcast-fill
//                     A[:,k]*w with float4 stores. Pure HBM-write bound.
// ============================================================================

#define MAX_K 1024

__device__ float d_Lp[MAX_K];
__device__ int   d_cum[MAX_K + 1];
__device__ int   d_total;
__device__ float d_lmaxf;

// ---------------------------------------------------------------------------
// Planning kernel: one block, blockDim = next pow2 >= K.
// ---------------------------------------------------------------------------
__global__ void plan_kernel(const float* __restrict__ L, int K, float Tf)
{
    __shared__ float shf[MAX_K];
    __shared__ int   shi[MAX_K];

    const int t  = threadIdx.x;
    const int nt = blockDim.x;      // power of two

    // ---- softmax max-reduce ----
    float lv = (t < K) ? L[t] : -INFINITY;
    shf[t] = lv;
    __syncthreads();
    for (int s = nt >> 1; s > 0; s >>= 1) {
        if (t < s) shf[t] = fmaxf(shf[t], shf[t + s]);
        __syncthreads();
    }
    const float mx = shf[0];
    __syncthreads();

    // ---- exp + sum-reduce ----
    float e = (t < K) ? expf(lv - mx) : 0.0f;
    shf[t] = e;
    __syncthreads();
    for (int s = nt >> 1; s > 0; s >>= 1) {
        if (t < s) shf[t] += shf[t + s];
        __syncthreads();
    }
    const float sum = shf[0];
    __syncthreads();

    // Lp = T * softmax(L)
    const float Lp = Tf * __fdiv_rn(e, sum);
    if (t < K) d_Lp[t] = Lp;

    // ---- l_max = int(max(Lp) + 0.5) ----
    shf[t] = (t < K) ? Lp : -INFINITY;
    __syncthreads();
    for (int s = nt >> 1; s > 0; s >>= 1) {
        if (t < s) shf[t] = fmaxf(shf[t], shf[t + s]);
        __syncthreads();
    }
    if (t == 0) {
        double dm = (double)shf[0] + 0.5;
        long long lm = (long long)dm;   // truncation == floor for positive
        d_lmaxf = (float)lm;
    }
    __syncthreads();

    // ---- r = max(rint(Lp), 0), inclusive scan (Hillis-Steele) ----
    int r = 0;
    if (t < K) {
        r = (int)rintf(Lp);     // half-to-even, matches np.rint
        if (r < 0) r = 0;
    }
    shi[t] = r;
    __syncthreads();
    for (int s = 1; s < nt; s <<= 1) {
        int add = (t >= s) ? shi[t - s] : 0;
        __syncthreads();
        shi[t] += add;
        __syncthreads();
    }

    if (t == 0) d_cum[0] = 0;
    if (t < K)  d_cum[t + 1] = shi[t];
    if (t == K - 1) d_total = shi[t];
}

// ---------------------------------------------------------------------------
// Fill kernel. blockDim.x = 256 threads, each thread owns 4 consecutive
// output columns (float4 store). grid.x tiles T, grid.y tiles C.
// ---------------------------------------------------------------------------
__global__ void __launch_bounds__(256) fill_kernel(
    const float* __restrict__ A,
    float* __restrict__ out,
    int K, int T, int C, int c_per_block)
{
    const int tt0 = (blockIdx.x * blockDim.x + threadIdx.x) * 4;
    if (tt0 >= T) return;

    const int    total = d_total;
    const float  lmaxf = d_lmaxf;
    const double ratio = (double)total / (double)T;   // same rounding as numpy

    float wv[4];
    int   kv[4];

#pragma unroll
    for (int i = 0; i < 4; i++) {
        int tt = tt0 + i;
        if (tt > T - 1) tt = T - 1;

        // idx = min(floor(tt * (total/T)), total-1)  -- double, matches numpy
        long long slot = (long long)floor((double)tt * ratio);
        if (slot > (long long)(total - 1)) slot = total - 1;
        if (slot < 0) slot = 0;

        // binary search: k with cum[k] <= slot < cum[k+1]
        int lo = 0, hi = K;
        while (hi - lo > 1) {
            int mid = (lo + hi) >> 1;
            if ((long long)d_cum[mid] <= slot) lo = mid; else hi = mid;
        }
        const int k = lo;
        const int j = (int)(slot - (long long)d_cum[k]);

        const float Lp = d_Lp[k];
        // x = (2j+1)/l_max - 1 ; xs = (l_max/Lp)*x + (l_max-Lp)/Lp
        const float x  = __fadd_rn(__fdiv_rn(__fadd_rn(__fmul_rn(2.0f, (float)j), 1.0f), lmaxf), -1.0f);
        const float s  = __fdiv_rn(lmaxf, Lp);
        const float tl = __fdiv_rn(__fadd_rn(lmaxf, -Lp), Lp);
        const float xs = __fadd_rn(__fmul_rn(s, x), tl);
        // p = ((xs+1)*100 - 1)/2
        const float p  = __fmul_rn(__fadd_rn(__fmul_rn(__fadd_rn(xs, 1.0f), 100.0f), -1.0f), 0.5f);
        const float p0 = floorf(p);
        const float w1 = __fadd_rn(p, -p0);
        const float in0 = (p0 >=  0.0f && p0 <= 99.0f) ? 1.0f : 0.0f;
        const float in1 = (p0 >= -1.0f && p0 <= 98.0f) ? 1.0f : 0.0f;
        wv[i] = __fadd_rn(__fmul_rn(__fadd_rn(1.0f, -w1), in0), __fmul_rn(w1, in1));
        kv[i] = k;
    }

    const int c0 = blockIdx.y * c_per_block;
    int c1 = c0 + c_per_block;
    if (c1 > C) c1 = C;

    const bool vec = (tt0 + 3 < T);

    for (int c = c0; c < c1; ++c) {
        const float* Ar = A + (size_t)c * (size_t)K;
        float4 o;
        o.x = __ldg(Ar + kv[0]) * wv[0];
        o.y = __ldg(Ar + kv[1]) * wv[1];
        o.z = __ldg(Ar + kv[2]) * wv[2];
        o.w = __ldg(Ar + kv[3]) * wv[3];
        float* op = out + (size_t)c * (size_t)T + tt0;
        if (vec) {
            *reinterpret_cast<float4*>(op) = o;
        } else {
            if (tt0     < T) op[0] = o.x;
            if (tt0 + 1 < T) op[1] = o.y;
            if (tt0 + 2 < T) op[2] = o.z;
            if (tt0 + 3 < T) op[3] = o.w;
        }
    }
}

// ---------------------------------------------------------------------------
extern "C" void kernel_launch(void* const* d_in, const int* in_sizes, int n_in,
                              void* d_out, int out_size)
{
    const float* A = (const float*)d_in[0];   // [C, K]
    const float* L = (const float*)d_in[1];   // [K]

    const int K = in_sizes[1];
    const int C = in_sizes[0] / K;
    const int T = out_size / C;               // out is [1, C, T]

    // planning: one block, pow2 threads >= K (K <= MAX_K)
    int nthreads = 1;
    while (nthreads < K) nthreads <<= 1;
    if (nthreads > MAX_K) nthreads = MAX_K;
    plan_kernel<<<1, nthreads>>>(L, K, (float)T);

    // fill: 256 threads x 4 columns each = 1024 columns per block tile
    const int c_per_block = 32;
    dim3 block(256);
    dim3 grid((T + 1024 - 1) / 1024, (C + c_per_block - 1) / c_per_block);
    fill_kernel<<<grid, block>>>(A, (float*)d_out, K, T, C, c_per_block);
}

// round 2
// speedup vs baseline: 1.4947x; 1.4947x over previous
#include <cuda_runtime.h>
#include <math.h>
#include <stdint.h>

// ============================================================================
// TemporalSamplingUpSampler — 3-phase:
//   1) plan_kernel (1 block):  softmax -> Lp, lengths r = rint(Lp), prefix sum,
//                              total, l_max.
//   2) expand_kernel (T/1024): per output column tt: slot -> (k, weight w).
//                              Writes d_w[T], d_k[T].
//   3) fill_kernel (hot):      out[c,tt] = A[c,k[tt]] * w[tt]. Pure streaming:
//                              coalesced plan reads, broadcast A reads (fast
//                              path: one load per 4 columns when k uniform),
//                              float4 evict-first stores.
// ============================================================================

#define MAX_K 1024
#define MAX_T (1 << 18)

__device__ float d_Lp[MAX_K];
__device__ int   d_cum[MAX_K + 1];
__device__ int   d_total;
__device__ float d_lmaxf;

__device__ float d_w[MAX_T];
__device__ int   d_k[MAX_T];

// ---------------------------------------------------------------------------
// Planning kernel: one block, blockDim = next pow2 >= K.
// ---------------------------------------------------------------------------
__global__ void plan_kernel(const float* __restrict__ L, int K, float Tf)
{
    __shared__ float shf[MAX_K];
    __shared__ int   shi[MAX_K];

    const int t  = threadIdx.x;
    const int nt = blockDim.x;      // power of two

    // softmax max-reduce
    float lv = (t < K) ? L[t] : -INFINITY;
    shf[t] = lv;
    __syncthreads();
    for (int s = nt >> 1; s > 0; s >>= 1) {
        if (t < s) shf[t] = fmaxf(shf[t], shf[t + s]);
        __syncthreads();
    }
    const float mx = shf[0];
    __syncthreads();

    // exp + sum-reduce
    float e = (t < K) ? expf(lv - mx) : 0.0f;
    shf[t] = e;
    __syncthreads();
    for (int s = nt >> 1; s > 0; s >>= 1) {
        if (t < s) shf[t] += shf[t + s];
        __syncthreads();
    }
    const float sum = shf[0];
    __syncthreads();

    const float Lp = Tf * __fdiv_rn(e, sum);
    if (t < K) d_Lp[t] = Lp;

    // l_max = int(max(Lp) + 0.5)
    shf[t] = (t < K) ? Lp : -INFINITY;
    __syncthreads();
    for (int s = nt >> 1; s > 0; s >>= 1) {
        if (t < s) shf[t] = fmaxf(shf[t], shf[t + s]);
        __syncthreads();
    }
    if (t == 0) {
        double dm = (double)shf[0] + 0.5;
        long long lm = (long long)dm;   // trunc == floor for positive
        d_lmaxf = (float)lm;
    }
    __syncthreads();

    // r = max(rint(Lp), 0), inclusive scan
    int r = 0;
    if (t < K) {
        r = (int)rintf(Lp);
        if (r < 0) r = 0;
    }
    shi[t] = r;
    __syncthreads();
    for (int s = 1; s < nt; s <<= 1) {
        int add = (t >= s) ? shi[t - s] : 0;
        __syncthreads();
        shi[t] += add;
        __syncthreads();
    }

    if (t == 0) d_cum[0] = 0;
    if (t < K)  d_cum[t + 1] = shi[t];
    if (t == K - 1) d_total = shi[t];
}

// ---------------------------------------------------------------------------
// Expand kernel: per output column compute (k, w). 256 thr x 4 cols/thread.
// ---------------------------------------------------------------------------
__global__ void __launch_bounds__(256) expand_kernel(int K, int T)
{
    const int tt0 = (blockIdx.x * blockDim.x + threadIdx.x) * 4;
    if (tt0 >= T) return;

    const int    total = d_total;
    const float  lmaxf = d_lmaxf;
    const double ratio = (double)total / (double)T;   // numpy rounding

    float wv[4];
    int   kv[4];

#pragma unroll
    for (int i = 0; i < 4; i++) {
        int tt = tt0 + i;
        if (tt > T - 1) tt = T - 1;

        long long slot = (long long)floor((double)tt * ratio);
        if (slot > (long long)(total - 1)) slot = total - 1;
        if (slot < 0) slot = 0;

        int lo = 0, hi = K;
        while (hi - lo > 1) {
            int mid = (lo + hi) >> 1;
            if ((long long)d_cum[mid] <= slot) lo = mid; else hi = mid;
        }
        const int k = lo;
        const int j = (int)(slot - (long long)d_cum[k]);

        const float Lp = d_Lp[k];
        const float x  = __fadd_rn(__fdiv_rn(__fadd_rn(__fmul_rn(2.0f, (float)j), 1.0f), lmaxf), -1.0f);
        const float s  = __fdiv_rn(lmaxf, Lp);
        const float tl = __fdiv_rn(__fadd_rn(lmaxf, -Lp), Lp);
        const float xs = __fadd_rn(__fmul_rn(s, x), tl);
        const float p  = __fmul_rn(__fadd_rn(__fmul_rn(__fadd_rn(xs, 1.0f), 100.0f), -1.0f), 0.5f);
        const float p0 = floorf(p);
        const float w1 = __fadd_rn(p, -p0);
        const float in0 = (p0 >=  0.0f && p0 <= 99.0f) ? 1.0f : 0.0f;
        const float in1 = (p0 >= -1.0f && p0 <= 98.0f) ? 1.0f : 0.0f;
        wv[i] = __fadd_rn(__fmul_rn(__fadd_rn(1.0f, -w1), in0), __fmul_rn(w1, in1));
        kv[i] = k;
    }

    if (tt0 + 3 < T) {
        *reinterpret_cast<float4*>(&d_w[tt0]) = make_float4(wv[0], wv[1], wv[2], wv[3]);
        *reinterpret_cast<int4*>  (&d_k[tt0]) = make_int4(kv[0], kv[1], kv[2], kv[3]);
    } else {
        for (int i = 0; i < 4 && tt0 + i < T; i++) {
            d_w[tt0 + i] = wv[i];
            d_k[tt0 + i] = kv[i];
        }
    }
}

// ---------------------------------------------------------------------------
// Fill kernel (hot). 256 threads, 4 columns/thread, c_per_block rows.
// ---------------------------------------------------------------------------
__global__ void __launch_bounds__(256) fill_kernel(
    const float* __restrict__ A,
    float* __restrict__ out,
    int K, int T, int C, int c_per_block)
{
    const int tt0 = (blockIdx.x * blockDim.x + threadIdx.x) * 4;
    if (tt0 >= T) return;

    const bool vec = (tt0 + 3 < T);

    float4 w;
    int4   k;
    if (vec) {
        w = *reinterpret_cast<const float4*>(&d_w[tt0]);
        k = *reinterpret_cast<const int4*>  (&d_k[tt0]);
    } else {
        w = make_float4(d_w[tt0], 0.f, 0.f, 0.f);
        k = make_int4(d_k[tt0], 0, 0, 0);
        if (tt0 + 1 < T) { w.y = d_w[tt0 + 1]; k.y = d_k[tt0 + 1]; }
        if (tt0 + 2 < T) { w.z = d_w[tt0 + 2]; k.z = d_k[tt0 + 2]; }
    }

    const int c0 = blockIdx.y * c_per_block;
    int c1 = c0 + c_per_block;
    if (c1 > C) c1 = C;

    // k is monotone non-decreasing along tt: ends equal => all equal.
    const bool same = (k.x == k.w);

    if (same & vec) {
        const float* Ap = A + (size_t)c0 * (size_t)K + k.x;
        float* op = out + (size_t)c0 * (size_t)T + tt0;
#pragma unroll 4
        for (int c = c0; c < c1; ++c) {
            const float a = __ldg(Ap);
            float4 o = make_float4(a * w.x, a * w.y, a * w.z, a * w.w);
            __stcs(reinterpret_cast<float4*>(op), o);
            Ap += K;
            op += T;
        }
    } else {
        for (int c = c0; c < c1; ++c) {
            const float* Ar = A + (size_t)c * (size_t)K;
            float4 o;
            o.x = __ldg(Ar + k.x) * w.x;
            o.y = __ldg(Ar + k.y) * w.y;
            o.z = __ldg(Ar + k.z) * w.z;
            o.w = __ldg(Ar + k.w) * w.w;
            float* op = out + (size_t)c * (size_t)T + tt0;
            if (vec) {
                __stcs(reinterpret_cast<float4*>(op), o);
            } else {
                if (tt0     < T) op[0] = o.x;
                if (tt0 + 1 < T) op[1] = o.y;
                if (tt0 + 2 < T) op[2] = o.z;
                if (tt0 + 3 < T) op[3] = o.w;
            }
        }
    }
}

// ---------------------------------------------------------------------------
extern "C" void kernel_launch(void* const* d_in, const int* in_sizes, int n_in,
                              void* d_out, int out_size)
{
    const float* A = (const float*)d_in[0];   // [C, K]
    const float* L = (const float*)d_in[1];   // [K]

    const int K = in_sizes[1];
    const int C = in_sizes[0] / K;
    const int T = out_size / C;               // out is [1, C, T]

    int nthreads = 1;
    while (nthreads < K) nthreads <<= 1;
    if (nthreads > MAX_K) nthreads = MAX_K;
    plan_kernel<<<1, nthreads>>>(L, K, (float)T);

    const int cols_per_block = 256 * 4;
    const int gx = (T + cols_per_block - 1) / cols_per_block;

    expand_kernel<<<gx, 256>>>(K, T);

    const int c_per_block = 8;
    dim3 grid(gx, (C + c_per_block - 1) / c_per_block);
    fill_kernel<<<grid, 256>>>(A, (float*)d_out, K, T, C, c_per_block);
}

// round 3
// speedup vs baseline: 1.5500x; 1.0370x over previous
#include <cuda_runtime.h>
#include <math.h>
#include <stdint.h>

// ============================================================================
// TemporalSamplingUpSampler — 2-phase:
//   1) expand_kernel: warp 0 of EVERY block redundantly computes the plan
//      (softmax -> Lp, r = rint, prefix sum, total, l_max) with shfl warp
//      primitives (no __syncthreads), drops it in smem; then all threads
//      expand their 4 output columns: slot -> (k, w). Writes d_w[T], d_k[T].
//   2) fill_kernel (hot): out[c,tt] = A[c,k[tt]] * w[tt]. Coalesced plan
//      reads, broadcast A reads (single load per 4 cols when k uniform),
//      float4 evict-first stores. Pure HBM-write bound.
// ============================================================================

#define MAX_K 1024
#define MAX_T (1 << 18)

__device__ float d_w[MAX_T];
__device__ int   d_k[MAX_T];

// ---------------------------------------------------------------------------
// Warp-level plan: called by lanes 0..31 only. K <= 1024 (KPL <= 32).
// Fills s_Lp[K], s_cum[K+1]; lane 0 returns total/lmax via pointers.
// ---------------------------------------------------------------------------
__device__ __forceinline__ void warp_plan(
    const float* __restrict__ L, int K, float Tf,
    float* __restrict__ s_Lp, int* __restrict__ s_cum,
    int* __restrict__ s_total, float* __restrict__ s_lmax)
{
    const int lane = threadIdx.x;          // 0..31
    const int KPL  = (K + 31) >> 5;
    const int base = lane * KPL;

    // pass 1: max(L)
    float mx = -INFINITY;
    for (int i = 0; i < KPL; i++) {
        int k = base + i;
        if (k < K) mx = fmaxf(mx, __ldg(L + k));
    }
    for (int o = 16; o; o >>= 1) mx = fmaxf(mx, __shfl_xor_sync(0xffffffffu, mx, o));

    // pass 2: sum(exp)
    float sum = 0.0f;
    for (int i = 0; i < KPL; i++) {
        int k = base + i;
        if (k < K) sum += expf(__ldg(L + k) - mx);
    }
    for (int o = 16; o; o >>= 1) sum += __shfl_xor_sync(0xffffffffu, sum, o);

    // pass 3: Lp, max(Lp), lane-local length total
    float maxLp = -INFINITY;
    int lane_total = 0;
    for (int i = 0; i < KPL; i++) {
        int k = base + i;
        if (k < K) {
            float Lp = Tf * __fdiv_rn(expf(__ldg(L + k) - mx), sum);
            s_Lp[k] = Lp;
            maxLp = fmaxf(maxLp, Lp);
            int r = (int)rintf(Lp);        // half-to-even == np.rint
            if (r < 0) r = 0;
            lane_total += r;
        }
    }
    for (int o = 16; o; o >>= 1) maxLp = fmaxf(maxLp, __shfl_xor_sync(0xffffffffu, maxLp, o));

    // inclusive scan of lane_total across lanes
    int incl = lane_total;
    for (int o = 1; o < 32; o <<= 1) {
        int v = __shfl_up_sync(0xffffffffu, incl, o);
        if (lane >= o) incl += v;
    }
    const int excl = incl - lane_total;
    const int total = __shfl_sync(0xffffffffu, incl, 31);

    // pass 4: write cum
    int running = excl;
    for (int i = 0; i < KPL; i++) {
        int k = base + i;
        if (k < K) {
            int r = (int)rintf(s_Lp[k]);
            if (r < 0) r = 0;
            running += r;
            s_cum[k + 1] = running;
        }
    }
    if (lane == 0) {
        s_cum[0] = 0;
        *s_total = total;
        double dm = (double)maxLp + 0.5;
        *s_lmax = (float)(long long)dm;    // int(max+0.5), trunc==floor (>=0)
    }
}

// ---------------------------------------------------------------------------
// Expand kernel: 256 threads x 4 columns each. Plan recomputed per block.
// ---------------------------------------------------------------------------
__global__ void __launch_bounds__(256) expand_kernel(
    const float* __restrict__ L, int K, int T, float Tf)
{
    __shared__ float s_Lp[MAX_K];
    __shared__ int   s_cum[MAX_K + 1];
    __shared__ int   s_total;
    __shared__ float s_lmax;

    if (threadIdx.x < 32)
        warp_plan(L, K, Tf, s_Lp, s_cum, &s_total, &s_lmax);
    __syncthreads();

    const int tt0 = (blockIdx.x * blockDim.x + threadIdx.x) * 4;
    if (tt0 >= T) return;

    const int   total = s_total;
    const float lmaxf = s_lmax;

    // T power-of-two: slot = (tt*total) >> log2(T) is EXACT (== numpy double)
    const bool  pow2  = (T & (T - 1)) == 0;
    const int   shift = __ffs(T) - 1;
    const double ratio = (double)total / (double)T;

    float wv[4];
    int   kv[4];

#pragma unroll
    for (int i = 0; i < 4; i++) {
        int tt = tt0 + i;
        if (tt > T - 1) tt = T - 1;

        long long slot;
        if (pow2) {
            slot = ((long long)tt * (long long)total) >> shift;
        } else {
            slot = (long long)floor((double)tt * ratio);
        }
        if (slot > (long long)(total - 1)) slot = total - 1;
        if (slot < 0) slot = 0;

        // binary search over smem cum
        int lo = 0, hi = K;
        const int si = (int)slot;
        while (hi - lo > 1) {
            int mid = (lo + hi) >> 1;
            if (s_cum[mid] <= si) lo = mid; else hi = mid;
        }
        const int k = lo;
        const int j = si - s_cum[k];

        const float Lp = s_Lp[k];
        const float x  = __fadd_rn(__fdiv_rn(__fadd_rn(__fmul_rn(2.0f, (float)j), 1.0f), lmaxf), -1.0f);
        const float s  = __fdiv_rn(lmaxf, Lp);
        const float tl = __fdiv_rn(__fadd_rn(lmaxf, -Lp), Lp);
        const float xs = __fadd_rn(__fmul_rn(s, x), tl);
        const float p  = __fmul_rn(__fadd_rn(__fmul_rn(__fadd_rn(xs, 1.0f), 100.0f), -1.0f), 0.5f);
        const float p0 = floorf(p);
        const float w1 = __fadd_rn(p, -p0);
        const float in0 = (p0 >=  0.0f && p0 <= 99.0f) ? 1.0f : 0.0f;
        const float in1 = (p0 >= -1.0f && p0 <= 98.0f) ? 1.0f : 0.0f;
        wv[i] = __fadd_rn(__fmul_rn(__fadd_rn(1.0f, -w1), in0), __fmul_rn(w1, in1));
        kv[i] = k;
    }

    if (tt0 + 3 < T) {
        *reinterpret_cast<float4*>(&d_w[tt0]) = make_float4(wv[0], wv[1], wv[2], wv[3]);
        *reinterpret_cast<int4*>  (&d_k[tt0]) = make_int4(kv[0], kv[1], kv[2], kv[3]);
    } else {
        for (int i = 0; i < 4 && tt0 + i < T; i++) {
            d_w[tt0 + i] = wv[i];
            d_k[tt0 + i] = kv[i];
        }
    }
}

// ---------------------------------------------------------------------------
// Fill kernel (hot). 256 threads, 4 columns/thread, c_per_block rows.
// ---------------------------------------------------------------------------
__global__ void __launch_bounds__(256) fill_kernel(
    const float* __restrict__ A,
    float* __restrict__ out,
    int K, int T, int C, int c_per_block)
{
    const int tt0 = (blockIdx.x * blockDim.x + threadIdx.x) * 4;
    if (tt0 >= T) return;

    const bool vec = (tt0 + 3 < T);

    float4 w;
    int4   k;
    if (vec) {
        w = *reinterpret_cast<const float4*>(&d_w[tt0]);
        k = *reinterpret_cast<const int4*>  (&d_k[tt0]);
    } else {
        w = make_float4(d_w[tt0], 0.f, 0.f, 0.f);
        k = make_int4(d_k[tt0], 0, 0, 0);
        if (tt0 + 1 < T) { w.y = d_w[tt0 + 1]; k.y = d_k[tt0 + 1]; }
        if (tt0 + 2 < T) { w.z = d_w[tt0 + 2]; k.z = d_k[tt0 + 2]; }
    }

    const int c0 = blockIdx.y * c_per_block;
    int c1 = c0 + c_per_block;
    if (c1 > C) c1 = C;

    // k monotone non-decreasing: ends equal => all four equal.
    const bool same = (k.x == k.w);

    if (same & vec) {
        const float* Ap = A + (size_t)c0 * (size_t)K + k.x;
        float* op = out + (size_t)c0 * (size_t)T + tt0;
#pragma unroll 4
        for (int c = c0; c < c1; ++c) {
            const float a = __ldg(Ap);
            float4 o = make_float4(a * w.x, a * w.y, a * w.z, a * w.w);
            __stcs(reinterpret_cast<float4*>(op), o);
            Ap += K;
            op += T;
        }
    } else {
        for (int c = c0; c < c1; ++c) {
            const float* Ar = A + (size_t)c * (size_t)K;
            float4 o;
            o.x = __ldg(Ar + k.x) * w.x;
            o.y = __ldg(Ar + k.y) * w.y;
            o.z = __ldg(Ar + k.z) * w.z;
            o.w = __ldg(Ar + k.w) * w.w;
            float* op = out + (size_t)c * (size_t)T + tt0;
            if (vec) {
                __stcs(reinterpret_cast<float4*>(op), o);
            } else {
                if (tt0     < T) op[0] = o.x;
                if (tt0 + 1 < T) op[1] = o.y;
                if (tt0 + 2 < T) op[2] = o.z;
                if (tt0 + 3 < T) op[3] = o.w;
            }
        }
    }
}

// ---------------------------------------------------------------------------
extern "C" void kernel_launch(void* const* d_in, const int* in_sizes, int n_in,
                              void* d_out, int out_size)
{
    const float* A = (const float*)d_in[0];   // [C, K]
    const float* L = (const float*)d_in[1];   // [K]

    const int K = in_sizes[1];
    const int C = in_sizes[0] / K;
    const int T = out_size / C;               // out is [1, C, T]

    const int cols_per_block = 256 * 4;
    const int gx = (T + cols_per_block - 1) / cols_per_block;

    expand_kernel<<<gx, 256>>>(L, K, T, (float)T);

    const int c_per_block = 8;
    dim3 grid(gx, (C + c_per_block - 1) / c_per_block);
    fill_kernel<<<grid, 256>>>(A, (float*)d_out, K, T, C, c_per_block);
}